// round 8
// baseline (speedup 1.0000x reference)
#include <cuda_runtime.h>
#include <cuda_bf16.h>
#include <math.h>
#include <stdint.h>
#include <stddef.h>

#define BB   32
#define NN   196
#define TT   128
#define DIMG 768
#define DH   512
#define VV   10000
#define VPAD 10240

#define NCTA 148
#define NTHR 256

// ============================ scratch =======================================
__device__ float g_keys[BB * NN * DH];
__device__ float g_Wk[BB * NN * DH];
__device__ float g_X[BB * TT * 4 * DH];
__device__ float g_M2[DH * DIMG];          // attn_Wk @ kv_W
__device__ float g_bvec[DH];               // attn_Wk @ kv_b
__device__ float g_h[BB * DH];
__device__ float g_c[BB * DH];
__device__ float g_hwh[BB * DH];           // h @ attn_Wh^T (full vector per b)
__device__ float g_sc[BB * 256];           // exp(scores), pitch 256
__device__ float g_ctx[BB * DH];
__device__ float g_ph[4 * BB * 4 * DH];    // h@W_hh^T partials (4 k-slots of 128)
__device__ float g_pc[4 * BB * 4 * DH];    // ctx@W_ihctx^T partials

// bf16 3-seg split buffers (zero-init; padded rows stay zero)
__device__ __nv_bfloat16 s_patches2[BB * NN * 3 * DIMG];
__device__ __nv_bfloat16 s_kvW2[DH * 3 * DIMG];
__device__ __nv_bfloat16 s_M2b[DH * 3 * DIMG];
__device__ __nv_bfloat16 s_Xemb2[BB * TT * 3 * DH];
__device__ __nv_bfloat16 s_Wih2[(4 * DH) * 3 * DH];
__device__ __nv_bfloat16 s_H2[BB * TT * 3 * DH];
__device__ __nv_bfloat16 s_outW2[VPAD * 3 * DH];

// hierarchical grid barrier
__device__ unsigned g_cnt_grp[32];
__device__ unsigned g_cnt_root;
__device__ volatile unsigned g_epoch;

// ============================ helpers ========================================
__device__ __forceinline__ uint32_t smem_u32(const void* p) {
    uint32_t a;
    asm("{ .reg .u64 t; cvta.to.shared.u64 t, %1; cvt.u32.u64 %0, t; }"
        : "=r"(a) : "l"(p));
    return a;
}
__device__ __forceinline__ void ldsm_x4(uint32_t& r0, uint32_t& r1,
                                        uint32_t& r2, uint32_t& r3, uint32_t a) {
    asm volatile("ldmatrix.sync.aligned.m8n8.x4.shared.b16 {%0,%1,%2,%3}, [%4];"
                 : "=r"(r0), "=r"(r1), "=r"(r2), "=r"(r3) : "r"(a));
}
__device__ __forceinline__ void ldsm_x2(uint32_t& r0, uint32_t& r1, uint32_t a) {
    asm volatile("ldmatrix.sync.aligned.m8n8.x2.shared.b16 {%0,%1}, [%2];"
                 : "=r"(r0), "=r"(r1) : "r"(a));
}
__device__ __forceinline__ void mma16816(float* c, const uint32_t* a,
                                         const uint32_t* b) {
    asm volatile(
        "mma.sync.aligned.m16n8k16.row.col.f32.bf16.bf16.f32 "
        "{%0,%1,%2,%3}, {%4,%5,%6,%7}, {%8,%9}, {%0,%1,%2,%3};"
        : "+f"(c[0]), "+f"(c[1]), "+f"(c[2]), "+f"(c[3])
        : "r"(a[0]), "r"(a[1]), "r"(a[2]), "r"(a[3]), "r"(b[0]), "r"(b[1]));
}
__device__ __forceinline__ void cp16(uint32_t dst, const void* src) {
    asm volatile("cp.async.cg.shared.global [%0], [%1], 16;"
                 :: "r"(dst), "l"(src));
}

__device__ __forceinline__ float tanh_fma(float x) {
    float t = fminf(fmaxf(x, -7.90531110763549805f), 7.90531110763549805f);
    float x2 = t * t;
    float p = -2.76076847742355e-16f;
    p = fmaf(p, x2,  2.00018790482477e-13f);
    p = fmaf(p, x2, -8.60467152213735e-11f);
    p = fmaf(p, x2,  5.12229709037114e-08f);
    p = fmaf(p, x2,  1.48572235717979e-05f);
    p = fmaf(p, x2,  6.37261928875436e-04f);
    p = fmaf(p, x2,  4.89352455891786e-03f);
    p = p * t;
    float q = 1.19825839466702e-06f;
    q = fmaf(q, x2, 1.18534705686654e-04f);
    q = fmaf(q, x2, 2.26843463243900e-03f);
    q = fmaf(q, x2, 4.89352518554385e-03f);
    float r = __uint_as_float(0x7EF311C3u - __float_as_uint(q));
    r = r * fmaf(-q, r, 2.0f);
    r = r * fmaf(-q, r, 2.0f);
    r = r * fmaf(-q, r, 2.0f);
    return p * r;
}
__device__ __forceinline__ float sigmoidf_acc(float x) {
    return 1.0f / (1.0f + expf(-x));
}
__device__ __forceinline__ float warp_sum(float v) {
#pragma unroll
    for (int o = 16; o > 0; o >>= 1) v += __shfl_xor_sync(0xffffffffu, v, o);
    return v;
}
__device__ __forceinline__ float block_sum256(float v, float* red) {
    int w = threadIdx.x >> 5, l = threadIdx.x & 31;
    v = warp_sum(v);
    if (l == 0) red[w] = v;
    __syncthreads();
    float r = red[0] + red[1] + red[2] + red[3] + red[4] + red[5] + red[6] + red[7];
    __syncthreads();
    return r;
}

#define NGRP ((NCTA + 7) / 8)
__device__ __forceinline__ void grid_barrier() {
    __threadfence();
    __syncthreads();
    if (threadIdx.x == 0) {
        unsigned e = g_epoch;
        unsigned g = (unsigned)blockIdx.x >> 3;
        unsigned gsz = (g == NGRP - 1) ? (NCTA - g * 8) : 8u;
        if (atomicAdd(&g_cnt_grp[g], 1u) == gsz - 1) {
            atomicExch(&g_cnt_grp[g], 0u);
            __threadfence();
            if (atomicAdd(&g_cnt_root, 1u) == NGRP - 1) {
                atomicExch(&g_cnt_root, 0u);
                __threadfence();
                g_epoch = e + 1;
            } else {
                while (g_epoch == e) { }
            }
        } else {
            while (g_epoch == e) { }
        }
        __threadfence();
    }
    __syncthreads();
}

// A-mode: [hi|lo|hi] ; B-mode: [hi|hi|lo]
__device__ __forceinline__ void split_one(float x, __nv_bfloat16* dst,
                                          size_t base, int K, int k, int modeB) {
    __nv_bfloat16 hi = __float2bfloat16(x);
    __nv_bfloat16 lo = __float2bfloat16(x - __bfloat162float(hi));
    dst[base + k] = hi;
    dst[base + K + k] = modeB ? hi : lo;
    dst[base + 2 * K + k] = modeB ? lo : hi;
}

// ============================ launch 1: mega =================================
// blocks [0,96): M2 = attn_Wk @ kv_W (64x64 tiles)
// blocks [96,104): bvec = attn_Wk @ kv_b
// blocks [104,...): grid-stride elementwise splits + gather
#define C1 (DH * DIMG)                    // kvW
#define C2 (C1 + (4 * DH) * DH)           // Wih x-half
#define C3 (C2 + VV * DH)                 // outW
#define C4 (C3 + BB * NN * DIMG)          // patches
#define C5 (C4 + BB * TT * DH)            // Xemb gather
__global__ __launch_bounds__(256) void mega(
    const float* __restrict__ patches, const int* __restrict__ tgt,
    const float* __restrict__ emb, const float* __restrict__ kv_W,
    const float* __restrict__ kv_b, const float* __restrict__ attn_Wk,
    const float* __restrict__ W_ih, const float* __restrict__ out_W)
{
    int bid = blockIdx.x, tid = threadIdx.x;
    if (bid < 96) {
        // M2 tile 64x64: M2[i,j] = sum_k Wk[i,k]*kvW[k,j]
        __shared__ float sa[16][65], sb[16][65];
        int i0 = (bid / 12) * 64, j0 = (bid % 12) * 64;
        float acc[4][4];
#pragma unroll
        for (int a = 0; a < 4; a++)
#pragma unroll
            for (int b = 0; b < 4; b++) acc[a][b] = 0.0f;
        int oi = (tid >> 4) * 4, oj = (tid & 15) * 4;
        for (int k0 = 0; k0 < DH; k0 += 16) {
#pragma unroll
            for (int q = 0; q < 4; q++) {
                int e = tid + q * 256;
                int ii = e & 63, kk = e >> 6;
                sa[kk][ii] = attn_Wk[(size_t)(i0 + ii) * DH + k0 + kk];
                sb[kk][ii] = kv_W[(size_t)(k0 + kk) * DIMG + j0 + ii];
            }
            __syncthreads();
#pragma unroll
            for (int kk = 0; kk < 16; kk++) {
                float av[4], bv[4];
#pragma unroll
                for (int a = 0; a < 4; a++) av[a] = sa[kk][oi + a];
#pragma unroll
                for (int b = 0; b < 4; b++) bv[b] = sb[kk][oj + b];
#pragma unroll
                for (int a = 0; a < 4; a++)
#pragma unroll
                    for (int b = 0; b < 4; b++)
                        acc[a][b] = fmaf(av[a], bv[b], acc[a][b]);
            }
            __syncthreads();
        }
#pragma unroll
        for (int a = 0; a < 4; a++)
#pragma unroll
            for (int b = 0; b < 4; b++)
                g_M2[(size_t)(i0 + oi + a) * DIMG + j0 + oj + b] = acc[a][b];
        return;
    }
    if (bid < 104) {
        if (tid < 64) {
            int i = (bid - 96) * 64 + tid;
            float s = 0.0f;
            for (int k = 0; k < DH; k++)
                s = fmaf(attn_Wk[(size_t)i * DH + k], kv_b[k], s);
            g_bvec[i] = s;
        }
        return;
    }
    // elementwise splits
    long stride = (long)(gridDim.x - 104) * 256;
    for (long idx = (long)(bid - 104) * 256 + tid; idx < C5; idx += stride) {
        if (idx < C1) {
            int r = (int)(idx / DIMG), k = (int)(idx % DIMG);
            split_one(kv_W[(size_t)r * DIMG + k], s_kvW2,
                      (size_t)r * (3 * DIMG), DIMG, k, 1);
        } else if (idx < C2) {
            long j = idx - C1;
            int r = (int)(j / DH), k = (int)(j % DH);
            split_one(W_ih[(size_t)r * (2 * DH) + k], s_Wih2,
                      (size_t)r * (3 * DH), DH, k, 1);
        } else if (idx < C3) {
            long j = idx - C2;
            int r = (int)(j / DH), k = (int)(j % DH);
            split_one(out_W[(size_t)r * DH + k], s_outW2,
                      (size_t)r * (3 * DH), DH, k, 1);
        } else if (idx < C4) {
            long j = idx - C3;
            int r = (int)(j / DIMG), k = (int)(j % DIMG);
            split_one(patches[(size_t)r * DIMG + k], s_patches2,
                      (size_t)r * (3 * DIMG), DIMG, k, 0);
        } else {
            long j = idx - C4;
            int r = (int)(j / DH), k = (int)(j % DH);
            float x = emb[(size_t)tgt[r] * DH + k];
            split_one(x, s_Xemb2, (size_t)r * (3 * DH), DH, k, 0);
        }
    }
}

// ============================ launch 2: split M2 =============================
__global__ __launch_bounds__(256) void split_m2() {
    int idx = blockIdx.x * 256 + threadIdx.x;
    if (idx >= DH * DIMG) return;
    int r = idx / DIMG, k = idx - r * DIMG;
    split_one(g_M2[(size_t)r * DIMG + k], s_M2b, (size_t)r * (3 * DIMG), DIMG, k, 1);
}

// ============================ gemm v2 (cp.async, grouped) ====================
struct GProb {
    const __nv_bfloat16* A; const __nv_bfloat16* B;
    const float* bias; float* C;
    int lda, ldb, ldc, Nc, tilesX, base, ns;   // ns = K/32
};
struct GProbs { GProb p[3]; int n; };

#define STG_ELEMS 10240      // A 128*40 + B 128*40
__global__ __launch_bounds__(256, 2) void gemm_v2(GProbs gp) {
    extern __shared__ __nv_bfloat16 smem[];   // 3 stages
    int bid = blockIdx.x, tid = threadIdx.x;
    GProb pr = gp.p[0];
    if (gp.n > 1 && bid >= gp.p[1].base) pr = gp.p[1];
    if (gp.n > 2 && bid >= gp.p[2].base) pr = gp.p[2];
    int t = bid - pr.base;
    int m0 = (t / pr.tilesX) * 128, n0 = (t % pr.tilesX) * 128;

    int lane = tid & 31, warp = tid >> 5;
    int wm = warp & 1, wn = warp >> 1;        // warp tile 64m x 32n
    uint32_t sbase = smem_u32(smem);
    int arow = tid >> 2, aseg = tid & 3;      // this thread's load slots

    const __nv_bfloat16* Abase = pr.A + (size_t)m0 * pr.lda;
    const __nv_bfloat16* Bbase = pr.B + (size_t)n0 * pr.ldb;

    float acc[4][4][4];
#pragma unroll
    for (int i = 0; i < 4; i++)
#pragma unroll
        for (int j = 0; j < 4; j++)
#pragma unroll
            for (int q = 0; q < 4; q++) acc[i][j][q] = 0.0f;

    auto load_stage = [&](int s, int buf) {
        uint32_t dA = sbase + (uint32_t)(buf * STG_ELEMS) * 2;
        uint32_t dB = dA + 5120 * 2;
        const __nv_bfloat16* As = Abase + (size_t)s * 32;
        const __nv_bfloat16* Bs = Bbase + (size_t)s * 32;
#pragma unroll
        for (int i = 0; i < 2; i++) {
            int row = arow + i * 64;
            cp16(dA + (uint32_t)(row * 40 + aseg * 8) * 2,
                 As + (size_t)row * pr.lda + aseg * 8);
            cp16(dB + (uint32_t)(row * 40 + aseg * 8) * 2,
                 Bs + (size_t)row * pr.ldb + aseg * 8);
        }
        asm volatile("cp.async.commit_group;" ::: "memory");
    };

    int ns = pr.ns;
    load_stage(0, 0);
    if (ns > 1) load_stage(1, 1);

    for (int s = 0; s < ns; s++) {
        if (s < ns - 1)
            asm volatile("cp.async.wait_group 1;" ::: "memory");
        else
            asm volatile("cp.async.wait_group 0;" ::: "memory");
        __syncthreads();
        if (s + 2 < ns) load_stage(s + 2, (s + 2) % 3);
        uint32_t bA = sbase + (uint32_t)((s % 3) * STG_ELEMS) * 2;
        uint32_t bB = bA + 5120 * 2;
#pragma unroll
        for (int kk2 = 0; kk2 < 2; kk2++) {
            int kk = kk2 * 16;
            uint32_t a[4][4];
#pragma unroll
            for (int mi = 0; mi < 4; mi++) {
                int row = wm * 64 + mi * 16 + (lane & 15);
                int col = kk + (lane >> 4) * 8;
                ldsm_x4(a[mi][0], a[mi][1], a[mi][2], a[mi][3],
                        bA + (uint32_t)(row * 40 + col) * 2);
            }
#pragma unroll
            for (int nj = 0; nj < 4; nj++) {
                uint32_t b[2];
                int row = wn * 32 + nj * 8 + (lane & 7);
                int col = kk + ((lane >> 3) & 1) * 8;
                ldsm_x2(b[0], b[1], bB + (uint32_t)(row * 40 + col) * 2);
#pragma unroll
                for (int mi = 0; mi < 4; mi++) mma16816(acc[mi][nj], a[mi], b);
            }
        }
        __syncthreads();
    }

#pragma unroll
    for (int mi = 0; mi < 4; mi++) {
        int mrow = m0 + wm * 64 + mi * 16 + (lane >> 2);
#pragma unroll
        for (int half = 0; half < 2; half++) {
            float* crow = pr.C + (size_t)(mrow + half * 8) * pr.ldc;
#pragma unroll
            for (int nj = 0; nj < 4; nj++) {
                int gn = n0 + wn * 32 + nj * 8 + (lane & 3) * 2;
                if (gn < pr.Nc) {
                    float2 v;
                    v.x = acc[mi][nj][half * 2 + 0] + (pr.bias ? pr.bias[gn] : 0.0f);
                    v.y = acc[mi][nj][half * 2 + 1] + (pr.bias ? pr.bias[gn + 1] : 0.0f);
                    *reinterpret_cast<float2*>(crow + gn) = v;
                }
            }
        }
    }
}

// ============================ skinny GEMM chunk ==============================
__device__ __forceinline__ void skinny_chunk(
    const float* __restrict__ A, int lda,
    const float* __restrict__ B, int ldb,
    float acc[8], float* sA, float* sB)
{
    int tid = threadIdx.x;
    __syncthreads();
#pragma unroll
    for (int i = tid; i < 32 * 64; i += 256) {
        int b = i >> 6, k = i & 63;
        sA[k * 36 + b] = A[(size_t)b * lda + k];
    }
#pragma unroll
    for (int i = tid; i < 64 * 64; i += 256) {
        int n = i >> 6, k = i & 63;
        sB[k * 65 + n] = B[(size_t)n * ldb + k];
    }
    __syncthreads();
    int nl = tid & 63, bq = tid >> 6;
#pragma unroll 8
    for (int k = 0; k < 64; k++) {
        float w = sB[k * 65 + nl];
        const float4* ap = reinterpret_cast<const float4*>(&sA[k * 36 + bq * 8]);
        float4 a0 = ap[0], a1 = ap[1];
        acc[0] = fmaf(a0.x, w, acc[0]); acc[1] = fmaf(a0.y, w, acc[1]);
        acc[2] = fmaf(a0.z, w, acc[2]); acc[3] = fmaf(a0.w, w, acc[3]);
        acc[4] = fmaf(a1.x, w, acc[4]); acc[5] = fmaf(a1.y, w, acc[5]);
        acc[6] = fmaf(a1.z, w, acc[6]); acc[7] = fmaf(a1.w, w, acc[7]);
    }
}

// ============================ launch 4: recurrence (4 phases/step) ===========
__global__ __launch_bounds__(NTHR) void recurrence(
    const float* __restrict__ cls,
    const float* __restrict__ ih_W, const float* __restrict__ ih_b,
    const float* __restrict__ ic_W, const float* __restrict__ ic_b,
    const float* __restrict__ attn_Wh, const float* __restrict__ attn_v,
    const float* __restrict__ W_ih, const float* __restrict__ W_hh,
    const float* __restrict__ b_ih, const float* __restrict__ b_hh,
    const float* __restrict__ lnw, const float* __restrict__ lnb)
{
    __shared__ float sh[64 * 36 + 64 * 65];   // 25.9 KB, aliased per phase
    float* sA = sh;
    float* sB = sh + 64 * 36;
    int tid = threadIdx.x;
    int cta = blockIdx.x;
    int nl = tid & 63, bq = tid >> 6;

    // ---- prologue: per-b h0, c0, hwh0 ----
    for (int b = cta; b < BB; b += NCTA) {
        float* scls = sh;          // 768
        float* hsm = sh + 768;     // 512
        for (int i = tid; i < DIMG; i += 256) scls[i] = cls[(size_t)b * DIMG + i];
        __syncthreads();
#pragma unroll
        for (int half = 0; half < 2; half++) {
            int d = tid + half * 256;
            float h0 = ih_b[d], c0 = ic_b[d];
            const float* wr = ih_W + (size_t)d * DIMG;
            const float* wc = ic_W + (size_t)d * DIMG;
            for (int k = 0; k < DIMG; k += 4) {
                h0 = fmaf(wr[k], scls[k], h0); h0 = fmaf(wr[k+1], scls[k+1], h0);
                h0 = fmaf(wr[k+2], scls[k+2], h0); h0 = fmaf(wr[k+3], scls[k+3], h0);
                c0 = fmaf(wc[k], scls[k], c0); c0 = fmaf(wc[k+1], scls[k+1], c0);
                c0 = fmaf(wc[k+2], scls[k+2], c0); c0 = fmaf(wc[k+3], scls[k+3], c0);
            }
            g_h[b * DH + d] = h0;
            g_c[b * DH + d] = c0;
            hsm[d] = h0;
        }
        __syncthreads();
#pragma unroll
        for (int half = 0; half < 2; half++) {
            int d = tid + half * 256;
            const float* wr = attn_Wh + (size_t)d * DH;
            float s = 0.0f;
            for (int k = 0; k < DH; k += 4) {
                s = fmaf(wr[k], hsm[k], s); s = fmaf(wr[k+1], hsm[k+1], s);
                s = fmaf(wr[k+2], hsm[k+2], s); s = fmaf(wr[k+3], hsm[k+3], s);
            }
            g_hwh[b * DH + d] = s;
        }
        __syncthreads();
    }
    grid_barrier();

    for (int t = 0; t < TT; t++) {
        // ---- P_A: scores+exp (tasks 0..127) and gatesh partials (128..255)
        for (int task = cta; task < 256; task += NCTA) {
            if (task < 128) {
                int b = task >> 2, n0 = (task & 3) * 49;
                float* hwhs = sh;
                float* vsm = sh + 512;
                __syncthreads();
#pragma unroll
                for (int d = tid; d < DH; d += 256) {
                    hwhs[d] = g_hwh[b * DH + d];
                    vsm[d] = attn_v[d];
                }
                __syncthreads();
                int w = tid >> 5, l = tid & 31;
                for (int n = n0 + w; n < n0 + 49; n += 8) {
                    const float* wk = &g_Wk[((size_t)b * NN + n) * DH];
                    float e = 0.0f;
#pragma unroll 4
                    for (int k = l; k < DH; k += 32)
                        e = fmaf(tanh_fma(hwhs[k] + wk[k]), vsm[k], e);
                    e = warp_sum(e);
                    if (l == 0) g_sc[b * 256 + n] = expf(e);   // |e| <= ~8, safe
                }
            } else {
                int idx = task - 128;
                int kslot = idx >> 5, n0 = (idx & 31) * 64, k0 = kslot * 128;
                float acc[8] = {0, 0, 0, 0, 0, 0, 0, 0};
                for (int kc = 0; kc < 2; kc++)
                    skinny_chunk(g_h + k0 + kc * 64, DH,
                                 W_hh + (size_t)n0 * DH + k0 + kc * 64, DH,
                                 acc, sA, sB);
#pragma unroll
                for (int j = 0; j < 8; j++)
                    g_ph[((size_t)kslot * BB + bq * 8 + j) * (4 * DH) + n0 + nl] = acc[j];
            }
        }
        grid_barrier();

        // ---- P_B: sum(e) + ctx (64 tasks)
        {
            float* alpha = sh;        // 256
            float* red = sh + 256;    // 8
            for (int task = cta; task < 64; task += NCTA) {
                int b = task >> 1, d0 = (task & 1) * 256;
                __syncthreads();
                float e = (tid < NN) ? g_sc[b * 256 + tid] : 0.0f;
                alpha[tid] = e;
                float ssum = block_sum256(e, red);
                float inv = 1.0f / ssum;
                int d = d0 + tid;
                const float* kb = &g_keys[(size_t)b * NN * DH + d];
                float a0 = 0.f, a1 = 0.f, a2 = 0.f, a3 = 0.f;
                float a4 = 0.f, a5 = 0.f, a6 = 0.f;
                for (int n = 0; n < NN; n += 7) {
                    a0 = fmaf(alpha[n + 0], kb[(size_t)(n + 0) * DH], a0);
                    a1 = fmaf(alpha[n + 1], kb[(size_t)(n + 1) * DH], a1);
                    a2 = fmaf(alpha[n + 2], kb[(size_t)(n + 2) * DH], a2);
                    a3 = fmaf(alpha[n + 3], kb[(size_t)(n + 3) * DH], a3);
                    a4 = fmaf(alpha[n + 4], kb[(size_t)(n + 4) * DH], a4);
                    a5 = fmaf(alpha[n + 5], kb[(size_t)(n + 5) * DH], a5);
                    a6 = fmaf(alpha[n + 6], kb[(size_t)(n + 6) * DH], a6);
                }
                float ctx = ((a0 + a1) + (a2 + a3)) + ((a4 + a5) + a6);
                g_ctx[b * DH + d] = ctx * inv;
            }
        }
        grid_barrier();

        // ---- P_C: gatesctx partials = ctx @ W_ihctx^T (128 tasks)
        for (int task = cta; task < 128; task += NCTA) {
            int kslot = task >> 5, n0 = (task & 31) * 64, k0 = kslot * 128;
            float acc[8] = {0, 0, 0, 0, 0, 0, 0, 0};
            for (int kc = 0; kc < 2; kc++)
                skinny_chunk(g_ctx + k0 + kc * 64, DH,
                             W_ih + (size_t)n0 * (2 * DH) + DH + k0 + kc * 64, 2 * DH,
                             acc, sA, sB);
#pragma unroll
            for (int j = 0; j < 8; j++)
                g_pc[((size_t)kslot * BB + bq * 8 + j) * (4 * DH) + n0 + nl] = acc[j];
        }
        grid_barrier();

        // ---- P_D: cell + LN + h/hwh/H2 (per-b, 32 tasks)
        {
            float* red = sh;           // 8
            float* hsm = sh + 16;      // 512
            for (int b = cta; b < BB; b += NCTA) {
                size_t xrow = ((size_t)b * TT + t) * (4 * DH);
                float hr[2], cn[2];
#pragma unroll
                for (int half = 0; half < 2; half++) {
                    int d = tid + half * 256;
                    float gi = 0.f, gf = 0.f, gg = 0.f, go = 0.f;
#pragma unroll
                    for (int s = 0; s < 4; s++) {
                        const float* p1 = g_ph + ((size_t)s * BB + b) * (4 * DH);
                        const float* p2 = g_pc + ((size_t)s * BB + b) * (4 * DH);
                        gi += p1[d] + p2[d];
                        gf += p1[DH + d] + p2[DH + d];
                        gg += p1[2 * DH + d] + p2[2 * DH + d];
                        go += p1[3 * DH + d] + p2[3 * DH + d];
                    }
                    const float* xp = g_X + xrow;
                    gi += xp[d] + b_ih[d] + b_hh[d];
                    gf += xp[DH + d] + b_ih[DH + d] + b_hh[DH + d];
                    gg += xp[2 * DH + d] + b_ih[2 * DH + d] + b_hh[2 * DH + d];
                    go += xp[3 * DH + d] + b_ih[3 * DH + d] + b_hh[3 * DH + d];
                    float c = g_c[b * DH + d];
                    cn[half] = sigmoidf_acc(gf) * c + sigmoidf_acc(gi) * tanh_fma(gg);
                    hr[half] = sigmoidf_acc(go) * tanh_fma(cn[half]);
                }
                __syncthreads();
                float mu = block_sum256(hr[0] + hr[1], red) * (1.0f / DH);
                float va = block_sum256(hr[0] * hr[0] + hr[1] * hr[1], red) * (1.0f / DH)
                           - mu * mu;
                float rstd = rsqrtf(va + 1e-5f);
                size_t h2row = ((size_t)b * TT + t) * (3 * DH);
#pragma unroll
                for (int half = 0; half < 2; half++) {
                    int d = tid + half * 256;
                    float hn = (hr[half] - mu) * rstd * lnw[d] + lnb[d];
                    g_c[b * DH + d] = cn[half];
                    g_h[b * DH + d] = hn;
                    hsm[d] = hn;
                    __nv_bfloat16 hi = __float2bfloat16(hn);
                    __nv_bfloat16 lo = __float2bfloat16(hn - __bfloat162float(hi));
                    s_H2[h2row + d] = hi;
                    s_H2[h2row + DH + d] = lo;
                    s_H2[h2row + 2 * DH + d] = hi;
                }
                __syncthreads();
                // hwh for next step
#pragma unroll
                for (int half = 0; half < 2; half++) {
                    int d = tid + half * 256;
                    const float* wr = attn_Wh + (size_t)d * DH;
                    float s0 = 0.f, s1 = 0.f;
                    for (int k = 0; k < DH; k += 8) {
                        s0 = fmaf(wr[k], hsm[k], s0);   s1 = fmaf(wr[k+1], hsm[k+1], s1);
                        s0 = fmaf(wr[k+2], hsm[k+2], s0); s1 = fmaf(wr[k+3], hsm[k+3], s1);
                        s0 = fmaf(wr[k+4], hsm[k+4], s0); s1 = fmaf(wr[k+5], hsm[k+5], s1);
                        s0 = fmaf(wr[k+6], hsm[k+6], s0); s1 = fmaf(wr[k+7], hsm[k+7], s1);
                    }
                    g_hwh[b * DH + d] = s0 + s1;
                }
                __syncthreads();
            }
        }
        grid_barrier();
    }
}

// ============================ launcher =======================================
extern "C" void kernel_launch(void* const* d_in, const int* in_sizes, int n_in,
                              void* d_out, int out_size)
{
    (void)in_sizes; (void)n_in; (void)out_size;
    const float* patches = (const float*)d_in[0];
    const float* cls     = (const float*)d_in[1];
    const int*   tgt     = (const int*)  d_in[2];
    const float* emb     = (const float*)d_in[3];
    const float* kv_W    = (const float*)d_in[4];
    const float* kv_b    = (const float*)d_in[5];
    const float* ih_W    = (const float*)d_in[6];
    const float* ih_b    = (const float*)d_in[7];
    const float* ic_W    = (const float*)d_in[8];
    const float* ic_b    = (const float*)d_in[9];
    const float* attn_Wh = (const float*)d_in[10];
    const float* attn_Wk = (const float*)d_in[11];
    const float* attn_v  = (const float*)d_in[12];
    const float* W_ih    = (const float*)d_in[13];
    const float* W_hh    = (const float*)d_in[14];
    const float* b_ih    = (const float*)d_in[15];
    const float* b_hh    = (const float*)d_in[16];
    const float* ln_w    = (const float*)d_in[17];
    const float* ln_b    = (const float*)d_in[18];
    const float* out_W   = (const float*)d_in[19];
    const float* out_b   = (const float*)d_in[20];
    float* out = (float*)d_out;

    float *p_keys, *p_Wk, *p_X, *p_bvec;
    cudaGetSymbolAddress((void**)&p_keys, g_keys);
    cudaGetSymbolAddress((void**)&p_Wk,   g_Wk);
    cudaGetSymbolAddress((void**)&p_X,    g_X);
    cudaGetSymbolAddress((void**)&p_bvec, g_bvec);
    __nv_bfloat16 *p_patches2, *p_kvW2, *p_M2b, *p_Xemb2, *p_Wih2, *p_H2, *p_outW2;
    cudaGetSymbolAddress((void**)&p_patches2, s_patches2);
    cudaGetSymbolAddress((void**)&p_kvW2,     s_kvW2);
    cudaGetSymbolAddress((void**)&p_M2b,      s_M2b);
    cudaGetSymbolAddress((void**)&p_Xemb2,    s_Xemb2);
    cudaGetSymbolAddress((void**)&p_Wih2,     s_Wih2);
    cudaGetSymbolAddress((void**)&p_H2,       s_H2);
    cudaGetSymbolAddress((void**)&p_outW2,    s_outW2);

    static int attr_set = 0;
    if (!attr_set) {
        cudaFuncSetAttribute(gemm_v2,
                             cudaFuncAttributeMaxDynamicSharedMemorySize,
                             3 * STG_ELEMS * 2);
        attr_set = 1;
    }

    // 1: mega (splits + gather + M2 + bvec)
    mega<<<104 + 8192, 256>>>(patches, tgt, emb, kv_W, kv_b, attn_Wk, W_ih, out_W);
    // 2: split M2
    split_m2<<<(DH * DIMG + 255) / 256, 256>>>();
    // 3: grouped GEMM — keys, Wk_keys, X
    {
        GProbs gp;
        gp.n = 3;
        gp.p[0] = { p_patches2, p_kvW2, kv_b, p_keys,
                    3 * DIMG, 3 * DIMG, DH, DH, 4, 0, (3 * DIMG) / 32 };
        gp.p[1] = { p_patches2, p_M2b, p_bvec, p_Wk,
                    3 * DIMG, 3 * DIMG, DH, DH, 4, 196, (3 * DIMG) / 32 };
        gp.p[2] = { p_Xemb2, p_Wih2, nullptr, p_X,
                    3 * DH, 3 * DH, 4 * DH, 4 * DH, 16, 392, (3 * DH) / 32 };
        gemm_v2<<<392 + 512, 256, 3 * STG_ELEMS * 2>>>(gp);
    }
    // 4: persistent recurrence  (profiled launch)
    recurrence<<<NCTA, NTHR>>>(cls, ih_W, ih_b, ic_W, ic_b,
                               attn_Wh, attn_v, W_ih, W_hh, b_ih, b_hh,
                               ln_w, ln_b);
    // 5: logits = H @ out_W^T + out_b
    {
        GProbs gp;
        gp.n = 1;
        gp.p[0] = { p_H2, p_outW2, out_b, out,
                    3 * DH, 3 * DH, VV, VV, VPAD / 128, 0, (3 * DH) / 32 };
        gp.p[1] = gp.p[0];
        gp.p[2] = gp.p[0];
        gemm_v2<<<(VPAD / 128) * ((BB * TT) / 128), 256, 3 * STG_ELEMS * 2>>>(gp);
    }
}